// round 14
// baseline (speedup 1.0000x reference)
#include <cuda_runtime.h>
#include <cuda_bf16.h>
#include <math.h>
#include <stdint.h>

#define EMBED   1024
#define NHEADS  16
#define HDIM    64
#define SEQ     2048
#define BATCH   2
#define MTOT    (BATCH * SEQ)      // 4096
#define QKVDIM  (3 * EMBED)        // 3072
#define GK      1024
// 0.125 * log2(e): scores produced directly in log2 domain for exp2f softmax
#define SC_Q    0.18033688011112042f

typedef unsigned long long u64;

// ---------------------------------------------------------------------------
// Scratch (allocation-free __device__ globals)
// ---------------------------------------------------------------------------
__device__ __align__(16) __nv_bfloat16 g_xh [(size_t)MTOT  * EMBED];
__device__ __align__(16) __nv_bfloat16 g_xl [(size_t)MTOT  * EMBED];
__device__ __align__(16) __nv_bfloat16 g_wqh[(size_t)QKVDIM* EMBED];
__device__ __align__(16) __nv_bfloat16 g_wql[(size_t)QKVDIM* EMBED];
__device__ __align__(16) __nv_bfloat16 g_woh[(size_t)EMBED * EMBED];
__device__ __align__(16) __nv_bfloat16 g_wol[(size_t)EMBED * EMBED];
__device__ __align__(16) __nv_bfloat16 g_qvh[(size_t)MTOT  * QKVDIM];
__device__ __align__(16) __nv_bfloat16 g_qvl[(size_t)MTOT  * QKVDIM];
__device__ __align__(16) __nv_bfloat16 g_ah [(size_t)MTOT  * EMBED];
__device__ __align__(16) __nv_bfloat16 g_al [(size_t)MTOT  * EMBED];

// ---------------------------------------------------------------------------
// helpers
// ---------------------------------------------------------------------------
__device__ __forceinline__ uint32_t smem_u32(const void* p) {
    uint32_t a;
    asm("{ .reg .u64 t; cvta.to.shared.u64 t, %1; cvt.u32.u64 %0, t; }" : "=r"(a) : "l"(p));
    return a;
}
__device__ __forceinline__ void cp16(uint32_t s, const void* g) {
    asm volatile("cp.async.cg.shared.global [%0], [%1], 16;" :: "r"(s), "l"(g));
}
__device__ __forceinline__ void mma2(float* c, const uint32_t* a, uint32_t b0, uint32_t b1) {
    asm("mma.sync.aligned.m16n8k16.row.col.f32.bf16.bf16.f32 "
        "{%0,%1,%2,%3}, {%4,%5,%6,%7}, {%8,%9}, {%0,%1,%2,%3};"
        : "+f"(c[0]), "+f"(c[1]), "+f"(c[2]), "+f"(c[3])
        : "r"(a[0]), "r"(a[1]), "r"(a[2]), "r"(a[3]), "r"(b0), "r"(b1));
}
__device__ __forceinline__ void ldsm4(uint32_t* r, uint32_t addr) {
    asm volatile("ldmatrix.sync.aligned.m8n8.x4.shared.b16 {%0,%1,%2,%3}, [%4];"
        : "=r"(r[0]), "=r"(r[1]), "=r"(r[2]), "=r"(r[3]) : "r"(addr));
}
__device__ __forceinline__ void ldsm4t(uint32_t* r, uint32_t addr) {
    asm volatile("ldmatrix.sync.aligned.m8n8.x4.trans.shared.b16 {%0,%1,%2,%3}, [%4];"
        : "=r"(r[0]), "=r"(r[1]), "=r"(r[2]), "=r"(r[3]) : "r"(addr));
}
__device__ __forceinline__ uint32_t packbf2(float lo, float hi) {
    uint32_t d;
    asm("cvt.rn.bf16x2.f32 %0, %1, %2;" : "=r"(d) : "f"(hi), "f"(lo));
    return d;
}
#define SWZ128(x) ((x) ^ (((x) >> 3) & 0x70))
// 64B logical rows interleaved into 128B macro rows, then SW128
#define TADDR(row, cb) SWZ128((uint32_t)((((row) >> 1) * 128) + (((row) & 1) * 64) + (cb)))

// ---------------------------------------------------------------------------
// fp32 -> (bf16 hi, bf16 lo) split
// ---------------------------------------------------------------------------
__global__ void cvt_split(const float* __restrict__ in, __nv_bfloat16* __restrict__ hi,
                          __nv_bfloat16* __restrict__ lo, int n4)
{
    int i = blockIdx.x * blockDim.x + threadIdx.x;
    if (i >= n4) return;
    float4 v = reinterpret_cast<const float4*>(in)[i];
    float h0 = __bfloat162float(__float2bfloat16(v.x));
    float h1 = __bfloat162float(__float2bfloat16(v.y));
    float h2 = __bfloat162float(__float2bfloat16(v.z));
    float h3 = __bfloat162float(__float2bfloat16(v.w));
    uint2 hv, lv;
    hv.x = packbf2(v.x, v.y);      hv.y = packbf2(v.z, v.w);
    lv.x = packbf2(v.x - h0, v.y - h1);
    lv.y = packbf2(v.z - h2, v.w - h3);
    reinterpret_cast<uint2*>(hi)[i] = hv;
    reinterpret_cast<uint2*>(lo)[i] = lv;
}

__device__ __forceinline__ void store_split(__nv_bfloat16* Ch, __nv_bfloat16* Cl,
                                            size_t off, float v0, float v1)
{
    float h0 = __bfloat162float(__float2bfloat16(v0));
    float h1 = __bfloat162float(__float2bfloat16(v1));
    *reinterpret_cast<uint32_t*>(&Ch[off]) = packbf2(v0, v1);
    *reinterpret_cast<uint32_t*>(&Cl[off]) = packbf2(v0 - h0, v1 - h1);
}

// ---------------------------------------------------------------------------
// HMMA bf16x3 GEMM v7: CTA 64x128 (M x N), 128 threads (4 warps, each 16x128),
// BK=32 -> 96 MMAs per chunk per warp (2x longer runs between barriers).
// 3-stage cp.async (depth-2 prefetch), 3 CTAs/SM.
// MODE 0: fp32 out + bias. MODE 1: split hi/lo out, cols<qcols scaled SC_Q.
// ---------------------------------------------------------------------------
#define AH_O   0
#define AL_O   4096
#define BH_O   8192
#define BL_O   16384
#define STG_B  24576                // bytes per stage (A 2x4KB + B 2x8KB)
#define NSTG   3
#define GEMM_SMEM (NSTG * STG_B)    // 72 KB

template<int MODE>
__global__ __launch_bounds__(128, 3)
void gemm_bf16x3(const __nv_bfloat16* __restrict__ Ah, const __nv_bfloat16* __restrict__ Al,
                 const __nv_bfloat16* __restrict__ Bh, const __nv_bfloat16* __restrict__ Bl,
                 const float* __restrict__ bias, float* __restrict__ C,
                 __nv_bfloat16* __restrict__ Ch, __nv_bfloat16* __restrict__ Cl,
                 int M, int N, int K, int qcols)
{
    extern __shared__ __align__(16) char sm[];
    const uint32_t sb = smem_u32(sm);

    const int tid  = threadIdx.x;
    const int wid  = tid >> 5, lane = tid & 31;
    const int bm   = blockIdx.y * 64, bn = blockIdx.x * 128;
    const int wr   = wid * 16;
    const int g    = lane >> 2;
    const int cp2  = (lane & 3) * 2;
    const int m_   = lane >> 3, r_ = lane & 7;

    const __nv_bfloat16* aSrc[2] = { Ah + (size_t)bm * K, Al + (size_t)bm * K };
    const __nv_bfloat16* bSrc[2] = { Bh + (size_t)bn * K, Bl + (size_t)bn * K };

    // ---- hoisted cp.async addresses ----
    const int lrow = tid >> 2, lcc = tid & 3;      // 32 rows per pass, 4x16B per row
    size_t  aroff[2];  uint32_t asoff[2];
#pragma unroll
    for (int it = 0; it < 2; it++) {
        int row = lrow + it * 32;
        aroff[it] = (size_t)row * K + lcc * 8;
        asoff[it] = TADDR(row, lcc * 16);
    }
    size_t  broff[4];  uint32_t bsoff[4];
#pragma unroll
    for (int it = 0; it < 4; it++) {
        int row = lrow + it * 32;
        broff[it] = (size_t)row * K + lcc * 8;
        bsoff[it] = TADDR(row, lcc * 16);
    }

    // ---- hoisted ldmatrix offsets (kk=0; kk=1 is ^32) ----
    const int cb0 = (m_ >> 1) * 16;
    uint32_t aoff[2], bhoff[8], bloff[8];
    {
        int row = wr + (m_ & 1) * 8 + r_;
        aoff[0] = (uint32_t)AH_O + TADDR(row, cb0);
        aoff[1] = (uint32_t)AL_O + TADDR(row, cb0);
    }
#pragma unroll
    for (int ntp = 0; ntp < 8; ntp++) {
        int row = ntp * 16 + (m_ & 1) * 8 + r_;
        bhoff[ntp] = (uint32_t)BH_O + TADDR(row, cb0);
        bloff[ntp] = (uint32_t)BL_O + TADDR(row, cb0);
    }

    float acc[16][4];
#pragma unroll
    for (int j = 0; j < 16; j++)
#pragma unroll
        for (int l = 0; l < 4; l++) acc[j][l] = 0.f;

    const int nch = K >> 5;     // 32

    auto stage_load = [&](int c, int slot) {
        const uint32_t stg = sb + (uint32_t)(slot * STG_B);
        const size_t koff = (size_t)c * 32;
#pragma unroll
        for (int it = 0; it < 2; it++) {
            cp16(stg + AH_O + asoff[it], aSrc[0] + aroff[it] + koff);
            cp16(stg + AL_O + asoff[it], aSrc[1] + aroff[it] + koff);
        }
#pragma unroll
        for (int it = 0; it < 4; it++) {
            cp16(stg + BH_O + bsoff[it], bSrc[0] + broff[it] + koff);
            cp16(stg + BL_O + bsoff[it], bSrc[1] + broff[it] + koff);
        }
        asm volatile("cp.async.commit_group;");
    };

    stage_load(0, 0);
    stage_load(1, 1);

    int slot_c  = 0;
    int slot_nx = 2;

    for (int c = 0; c < nch; c++) {
        if (c + 1 < nch) asm volatile("cp.async.wait_group 1;");
        else             asm volatile("cp.async.wait_group 0;");
        __syncthreads();

        if (c + 2 < nch) {
            stage_load(c + 2, slot_nx);
            if (++slot_nx == NSTG) slot_nx = 0;
        }

        const uint32_t stg = sb + (uint32_t)(slot_c * STG_B);
        if (++slot_c == NSTG) slot_c = 0;

#pragma unroll
        for (int kk = 0; kk < 2; kk++) {
            const uint32_t kx = kk ? 32u : 0u;
            uint32_t af[2][4];
            ldsm4(af[0], stg + (aoff[0] ^ kx));
            ldsm4(af[1], stg + (aoff[1] ^ kx));
#pragma unroll
            for (int ntp = 0; ntp < 8; ntp++) {
                uint32_t bh[4], bl[4];
                ldsm4(bh, stg + (bhoff[ntp] ^ kx));
                ldsm4(bl, stg + (bloff[ntp] ^ kx));
                mma2(acc[2 * ntp],     af[0], bh[0], bh[2]);
                mma2(acc[2 * ntp + 1], af[0], bh[1], bh[3]);
                mma2(acc[2 * ntp],     af[0], bl[0], bl[2]);
                mma2(acc[2 * ntp + 1], af[0], bl[1], bl[3]);
                mma2(acc[2 * ntp],     af[1], bh[0], bh[2]);
                mma2(acc[2 * ntp + 1], af[1], bh[1], bh[3]);
            }
        }
    }

#pragma unroll
    for (int nt = 0; nt < 16; nt++) {
        int col = bn + nt * 8 + cp2;
        int r0  = bm + wr + g;
        if (MODE == 0) {
            float b0 = bias ? bias[col] : 0.f;
            float b1 = bias ? bias[col + 1] : 0.f;
            float2 v0 = make_float2(acc[nt][0] + b0, acc[nt][1] + b1);
            float2 v1 = make_float2(acc[nt][2] + b0, acc[nt][3] + b1);
            *reinterpret_cast<float2*>(&C[(size_t)r0 * N + col])       = v0;
            *reinterpret_cast<float2*>(&C[(size_t)(r0 + 8) * N + col]) = v1;
        } else {
            float sc = (col < qcols) ? SC_Q : 1.0f;
            store_split(Ch, Cl, (size_t)r0 * N + col,       acc[nt][0] * sc, acc[nt][1] * sc);
            store_split(Ch, Cl, (size_t)(r0 + 8) * N + col, acc[nt][2] * sc, acc[nt][3] * sc);
        }
    }
}

// ---------------------------------------------------------------------------
// HMMA flash attention (unchanged from passing R13): full bf16x3 numerics,
// exp2 softmax, CTA = 64 queries / 4 warps / 128 threads, 2 CTAs/SM.
// ---------------------------------------------------------------------------
#define QH_B   0
#define QL_B   8192
#define ASTG0  16384
#define ASTG   32768
#define KH_B   0
#define KL_B   8192
#define VH_B   16384
#define VL_B   24576
#define ATTN_SMEM (ASTG0 + 2 * ASTG + 1024)   // 81 KB

__global__ __launch_bounds__(128, 2)
void attn_mma(const __nv_bfloat16* __restrict__ qvh, const __nv_bfloat16* __restrict__ qvl,
              __nv_bfloat16* __restrict__ oh, __nv_bfloat16* __restrict__ ol)
{
    extern __shared__ __align__(16) char asmem[];
    const uint32_t sb = (smem_u32(asmem) + 1023u) & ~1023u;

    const int tid  = threadIdx.x;
    const int wid  = tid >> 5, lane = tid & 31;
    const int b    = blockIdx.z, h = blockIdx.y;
    const int q0   = blockIdx.x * 64;
    const int g    = lane >> 2, t4 = lane & 3;
    const int wr   = wid * 16;
    const int m_   = lane >> 3, r_ = lane & 7;

    {
        const size_t qb = ((size_t)(b * SEQ + q0)) * QKVDIM + h * HDIM;
#pragma unroll
        for (int it = 0; it < 4; it++) {
            int idx = tid + it * 128;
            int row = idx >> 3, c = idx & 7;
            uint32_t off = SWZ128((uint32_t)(row * 128 + c * 16));
            cp16(sb + QH_B + off, qvh + qb + (size_t)row * QKVDIM + c * 8);
            cp16(sb + QL_B + off, qvl + qb + (size_t)row * QKVDIM + c * 8);
        }
        asm volatile("cp.async.commit_group;");
    }

    auto stage_load = [&](int kt, int s) {
        const size_t kb = ((size_t)(b * SEQ + kt * 64)) * QKVDIM + h * HDIM;
        const __nv_bfloat16* srcs[4] = {
            qvh + kb + EMBED,     qvl + kb + EMBED,
            qvh + kb + 2 * EMBED, qvl + kb + 2 * EMBED };
#pragma unroll
        for (int t = 0; t < 4; t++) {
#pragma unroll
            for (int it = 0; it < 4; it++) {
                int idx = tid + it * 128;
                int row = idx >> 3, c = idx & 7;
                uint32_t off = SWZ128((uint32_t)(row * 128 + c * 16));
                cp16(sb + ASTG0 + s * ASTG + t * 8192 + off,
                     srcs[t] + (size_t)row * QKVDIM + c * 8);
            }
        }
        asm volatile("cp.async.commit_group;");
    };

    stage_load(0, 0);

    uint32_t qf[2][4][4];
    float oacc[8][4];
#pragma unroll
    for (int i = 0; i < 8; i++)
#pragma unroll
        for (int j = 0; j < 4; j++) oacc[i][j] = 0.f;
    float m0 = -INFINITY, m1 = -INFINITY, l0 = 0.f, l1 = 0.f;

    const int ntile = SEQ / 64;

    for (int c = 0; c < ntile; c++) {
        const int s = c & 1;
        if (c + 1 < ntile) {
            stage_load(c + 1, s ^ 1);
            asm volatile("cp.async.wait_group 1;");
        } else {
            asm volatile("cp.async.wait_group 0;");
        }
        __syncthreads();

        if (c == 0) {
#pragma unroll
            for (int hl = 0; hl < 2; hl++)
#pragma unroll
                for (int ks = 0; ks < 4; ks++) {
                    uint32_t off = SWZ128((uint32_t)(
                        (wr + (m_ & 1) * 8 + r_) * 128 + ks * 32 + (m_ >> 1) * 16));
                    ldsm4(qf[hl][ks], sb + (hl ? QL_B : QH_B) + off);
                }
        }

        const uint32_t stgb = sb + ASTG0 + s * ASTG;

        float sacc[8][4];
#pragma unroll
        for (int i = 0; i < 8; i++)
#pragma unroll
            for (int j = 0; j < 4; j++) sacc[i][j] = 0.f;

#pragma unroll
        for (int ks = 0; ks < 4; ks++) {
#pragma unroll
            for (int ntp = 0; ntp < 4; ntp++) {
                uint32_t off = SWZ128((uint32_t)(
                    (ntp * 16 + (m_ & 1) * 8 + r_) * 128 + ks * 32 + (m_ >> 1) * 16));
                uint32_t kh[4], kl[4];
                ldsm4(kh, stgb + KH_B + off);
                ldsm4(kl, stgb + KL_B + off);
                mma2(sacc[2 * ntp],     qf[0][ks], kh[0], kh[2]);
                mma2(sacc[2 * ntp + 1], qf[0][ks], kh[1], kh[3]);
                mma2(sacc[2 * ntp],     qf[0][ks], kl[0], kl[2]);
                mma2(sacc[2 * ntp + 1], qf[0][ks], kl[1], kl[3]);
                mma2(sacc[2 * ntp],     qf[1][ks], kh[0], kh[2]);
                mma2(sacc[2 * ntp + 1], qf[1][ks], kh[1], kh[3]);
            }
        }

        float tm0 = -INFINITY, tm1 = -INFINITY;
#pragma unroll
        for (int nt = 0; nt < 8; nt++) {
            tm0 = fmaxf(tm0, fmaxf(sacc[nt][0], sacc[nt][1]));
            tm1 = fmaxf(tm1, fmaxf(sacc[nt][2], sacc[nt][3]));
        }
        tm0 = fmaxf(tm0, __shfl_xor_sync(0xffffffffu, tm0, 1));
        tm0 = fmaxf(tm0, __shfl_xor_sync(0xffffffffu, tm0, 2));
        tm1 = fmaxf(tm1, __shfl_xor_sync(0xffffffffu, tm1, 1));
        tm1 = fmaxf(tm1, __shfl_xor_sync(0xffffffffu, tm1, 2));

        const float mn0 = fmaxf(m0, tm0), mn1 = fmaxf(m1, tm1);
        const float cr0 = exp2f(m0 - mn0), cr1 = exp2f(m1 - mn1);
        m0 = mn0; m1 = mn1;

        float rs0 = 0.f, rs1 = 0.f;
#pragma unroll
        for (int nt = 0; nt < 8; nt++) {
            sacc[nt][0] = exp2f(sacc[nt][0] - mn0); rs0 += sacc[nt][0];
            sacc[nt][1] = exp2f(sacc[nt][1] - mn0); rs0 += sacc[nt][1];
            sacc[nt][2] = exp2f(sacc[nt][2] - mn1); rs1 += sacc[nt][2];
            sacc[nt][3] = exp2f(sacc[nt][3] - mn1); rs1 += sacc[nt][3];
        }
        rs0 += __shfl_xor_sync(0xffffffffu, rs0, 1);
        rs0 += __shfl_xor_sync(0xffffffffu, rs0, 2);
        rs1 += __shfl_xor_sync(0xffffffffu, rs1, 1);
        rs1 += __shfl_xor_sync(0xffffffffu, rs1, 2);
        l0 = l0 * cr0 + rs0;
        l1 = l1 * cr1 + rs1;

#pragma unroll
        for (int nt = 0; nt < 8; nt++) {
            oacc[nt][0] *= cr0; oacc[nt][1] *= cr0;
            oacc[nt][2] *= cr1; oacc[nt][3] *= cr1;
        }

#pragma unroll
        for (int ks = 0; ks < 4; ks++) {
            const float* s0 = sacc[2 * ks];
            const float* s1 = sacc[2 * ks + 1];
            uint32_t pah[4], pal[4];
            {
                float v[8] = { s0[0], s0[1], s0[2], s0[3], s1[0], s1[1], s1[2], s1[3] };
#pragma unroll
                for (int i = 0; i < 4; i++) {
                    float x = v[2 * i], y = v[2 * i + 1];
                    float xh = __bfloat162float(__float2bfloat16(x));
                    float yh = __bfloat162float(__float2bfloat16(y));
                    pah[i] = packbf2(x, y);
                    pal[i] = packbf2(x - xh, y - yh);
                }
            }
#pragma unroll
            for (int ntp = 0; ntp < 4; ntp++) {
                uint32_t off = SWZ128((uint32_t)(
                    (ks * 16 + (m_ & 1) * 8 + r_) * 128 + ntp * 32 + (m_ >> 1) * 16));
                uint32_t vh[4], vl[4];
                ldsm4t(vh, stgb + VH_B + off);
                ldsm4t(vl, stgb + VL_B + off);
                mma2(oacc[2 * ntp],     pah, vh[0], vh[1]);
                mma2(oacc[2 * ntp + 1], pah, vh[2], vh[3]);
                mma2(oacc[2 * ntp],     pah, vl[0], vl[1]);
                mma2(oacc[2 * ntp + 1], pah, vl[2], vl[3]);
                mma2(oacc[2 * ntp],     pal, vh[0], vh[1]);
                mma2(oacc[2 * ntp + 1], pal, vh[2], vh[3]);
            }
        }
        __syncthreads();
    }

    const float il0 = 1.f / l0, il1 = 1.f / l1;
    const size_t ob0 = ((size_t)(b * SEQ + q0 + wr + g)) * EMBED + h * HDIM;
    const size_t ob1 = ob0 + (size_t)8 * EMBED;
#pragma unroll
    for (int nt = 0; nt < 8; nt++) {
        int d = nt * 8 + 2 * t4;
        store_split(oh, ol, ob0 + d, oacc[nt][0] * il0, oacc[nt][1] * il0);
        store_split(oh, ol, ob1 + d, oacc[nt][2] * il1, oacc[nt][3] * il1);
    }
}

// ---------------------------------------------------------------------------
extern "C" void kernel_launch(void* const* d_in, const int* in_sizes, int n_in,
                              void* d_out, int out_size)
{
    const float* x     = (const float*)d_in[0];
    const float* w_qkv = (const float*)d_in[1];
    const float* w_out = (const float*)d_in[2];
    const float* b_out = (const float*)d_in[3];
    float* out = (float*)d_out;

    __nv_bfloat16 *xh, *xl, *wqh, *wql, *woh, *wol, *qvh, *qvl, *ah, *al;
    cudaGetSymbolAddress((void**)&xh,  g_xh);  cudaGetSymbolAddress((void**)&xl,  g_xl);
    cudaGetSymbolAddress((void**)&wqh, g_wqh); cudaGetSymbolAddress((void**)&wql, g_wql);
    cudaGetSymbolAddress((void**)&woh, g_woh); cudaGetSymbolAddress((void**)&wol, g_wol);
    cudaGetSymbolAddress((void**)&qvh, g_qvh); cudaGetSymbolAddress((void**)&qvl, g_qvl);
    cudaGetSymbolAddress((void**)&ah,  g_ah);  cudaGetSymbolAddress((void**)&al,  g_al);

    cudaFuncSetAttribute(gemm_bf16x3<0>, cudaFuncAttributeMaxDynamicSharedMemorySize, GEMM_SMEM);
    cudaFuncSetAttribute(gemm_bf16x3<1>, cudaFuncAttributeMaxDynamicSharedMemorySize, GEMM_SMEM);
    cudaFuncSetAttribute(attn_mma, cudaFuncAttributeMaxDynamicSharedMemorySize, (int)ATTN_SMEM);

    // operand splits
    {
        int n4 = (MTOT * EMBED) / 4;
        cvt_split<<<(n4 + 255) / 256, 256>>>(x, xh, xl, n4);
    }
    {
        int n4 = (QKVDIM * EMBED) / 4;
        cvt_split<<<(n4 + 255) / 256, 256>>>(w_qkv, wqh, wql, n4);
    }
    {
        int n4 = (EMBED * EMBED) / 4;
        cvt_split<<<(n4 + 255) / 256, 256>>>(w_out, woh, wol, n4);
    }

    // 1) QKV projection -> split hi/lo, Q cols pre-scaled to log2 domain
    {
        dim3 grid(QKVDIM / 128, MTOT / 64);
        gemm_bf16x3<1><<<grid, 128, GEMM_SMEM>>>(xh, xl, wqh, wql, nullptr, nullptr,
                                                 qvh, qvl, MTOT, QKVDIM, GK, EMBED);
    }

    // 2) flash attention (HMMA, exp2 softmax, full bf16x3 compensation)
    {
        dim3 grid(SEQ / 64, NHEADS, BATCH);
        attn_mma<<<grid, 128, ATTN_SMEM>>>(qvh, qvl, ah, al);
    }

    // 3) output projection + bias -> fp32 out (single wave: 512 CTAs)
    {
        dim3 grid(EMBED / 128, MTOT / 64);
        gemm_bf16x3<0><<<grid, 128, GEMM_SMEM>>>(ah, al, woh, wol, b_out, out,
                                                 nullptr, nullptr, MTOT, EMBED, GK, 0);
    }
}

// round 15
// speedup vs baseline: 1.0732x; 1.0732x over previous
#include <cuda_runtime.h>
#include <cuda_bf16.h>
#include <math.h>
#include <stdint.h>

#define EMBED   1024
#define NHEADS  16
#define HDIM    64
#define SEQ     2048
#define BATCH   2
#define MTOT    (BATCH * SEQ)      // 4096
#define QKVDIM  (3 * EMBED)        // 3072
#define GK      1024
// 0.125 * log2(e): scores produced directly in log2 domain for exp2f softmax
#define SC_Q    0.18033688011112042f

typedef unsigned long long u64;

// ---------------------------------------------------------------------------
// Scratch (allocation-free __device__ globals)
// ---------------------------------------------------------------------------
__device__ __align__(16) __nv_bfloat16 g_xh [(size_t)MTOT  * EMBED];
__device__ __align__(16) __nv_bfloat16 g_xl [(size_t)MTOT  * EMBED];
__device__ __align__(16) __nv_bfloat16 g_wqh[(size_t)QKVDIM* EMBED];
__device__ __align__(16) __nv_bfloat16 g_wql[(size_t)QKVDIM* EMBED];
__device__ __align__(16) __nv_bfloat16 g_woh[(size_t)EMBED * EMBED];
__device__ __align__(16) __nv_bfloat16 g_wol[(size_t)EMBED * EMBED];
__device__ __align__(16) __nv_bfloat16 g_qvh[(size_t)MTOT  * QKVDIM];
__device__ __align__(16) __nv_bfloat16 g_qvl[(size_t)MTOT  * QKVDIM];
__device__ __align__(16) __nv_bfloat16 g_ah [(size_t)MTOT  * EMBED];
__device__ __align__(16) __nv_bfloat16 g_al [(size_t)MTOT  * EMBED];

// ---------------------------------------------------------------------------
// helpers
// ---------------------------------------------------------------------------
__device__ __forceinline__ uint32_t smem_u32(const void* p) {
    uint32_t a;
    asm("{ .reg .u64 t; cvta.to.shared.u64 t, %1; cvt.u32.u64 %0, t; }" : "=r"(a) : "l"(p));
    return a;
}
__device__ __forceinline__ void cp16(uint32_t s, const void* g) {
    asm volatile("cp.async.cg.shared.global [%0], [%1], 16;" :: "r"(s), "l"(g));
}
__device__ __forceinline__ void mma2(float* c, const uint32_t* a, uint32_t b0, uint32_t b1) {
    asm("mma.sync.aligned.m16n8k16.row.col.f32.bf16.bf16.f32 "
        "{%0,%1,%2,%3}, {%4,%5,%6,%7}, {%8,%9}, {%0,%1,%2,%3};"
        : "+f"(c[0]), "+f"(c[1]), "+f"(c[2]), "+f"(c[3])
        : "r"(a[0]), "r"(a[1]), "r"(a[2]), "r"(a[3]), "r"(b0), "r"(b1));
}
__device__ __forceinline__ void ldsm4(uint32_t* r, uint32_t addr) {
    asm volatile("ldmatrix.sync.aligned.m8n8.x4.shared.b16 {%0,%1,%2,%3}, [%4];"
        : "=r"(r[0]), "=r"(r[1]), "=r"(r[2]), "=r"(r[3]) : "r"(addr));
}
__device__ __forceinline__ void ldsm4t(uint32_t* r, uint32_t addr) {
    asm volatile("ldmatrix.sync.aligned.m8n8.x4.trans.shared.b16 {%0,%1,%2,%3}, [%4];"
        : "=r"(r[0]), "=r"(r[1]), "=r"(r[2]), "=r"(r[3]) : "r"(addr));
}
__device__ __forceinline__ uint32_t packbf2(float lo, float hi) {
    uint32_t d;
    asm("cvt.rn.bf16x2.f32 %0, %1, %2;" : "=r"(d) : "f"(hi), "f"(lo));
    return d;
}
#define SWZ128(x) ((x) ^ (((x) >> 3) & 0x70))
// 64B logical rows interleaved into 128B macro rows, then SW128
#define TADDR(row, cb) SWZ128((uint32_t)((((row) >> 1) * 128) + (((row) & 1) * 64) + (cb)))

// ---------------------------------------------------------------------------
// fp32 -> (bf16 hi, bf16 lo) split
// ---------------------------------------------------------------------------
__global__ void cvt_split(const float* __restrict__ in, __nv_bfloat16* __restrict__ hi,
                          __nv_bfloat16* __restrict__ lo, int n4)
{
    int i = blockIdx.x * blockDim.x + threadIdx.x;
    if (i >= n4) return;
    float4 v = reinterpret_cast<const float4*>(in)[i];
    float h0 = __bfloat162float(__float2bfloat16(v.x));
    float h1 = __bfloat162float(__float2bfloat16(v.y));
    float h2 = __bfloat162float(__float2bfloat16(v.z));
    float h3 = __bfloat162float(__float2bfloat16(v.w));
    uint2 hv, lv;
    hv.x = packbf2(v.x, v.y);      hv.y = packbf2(v.z, v.w);
    lv.x = packbf2(v.x - h0, v.y - h1);
    lv.y = packbf2(v.z - h2, v.w - h3);
    reinterpret_cast<uint2*>(hi)[i] = hv;
    reinterpret_cast<uint2*>(lo)[i] = lv;
}

__device__ __forceinline__ void store_split(__nv_bfloat16* Ch, __nv_bfloat16* Cl,
                                            size_t off, float v0, float v1)
{
    float h0 = __bfloat162float(__float2bfloat16(v0));
    float h1 = __bfloat162float(__float2bfloat16(v1));
    *reinterpret_cast<uint32_t*>(&Ch[off]) = packbf2(v0, v1);
    *reinterpret_cast<uint32_t*>(&Cl[off]) = packbf2(v0 - h0, v1 - h1);
}

// ---------------------------------------------------------------------------
// HMMA bf16x3 GEMM (R13 config — best measured): CTA 64x64, 128 threads,
// BK=32, ldmatrix hoisted, 3-stage cp.async, 4 CTAs/SM.
// MODE 0: fp32 out + bias. MODE 1: split hi/lo out, cols<qcols scaled SC_Q.
// ---------------------------------------------------------------------------
#define AH_O   0
#define AL_O   4096
#define BH_O   8192
#define BL_O   12288
#define STG_B  16384                // bytes per stage
#define NSTG   3
#define GEMM_SMEM (NSTG * STG_B)    // 48 KB

template<int MODE>
__global__ __launch_bounds__(128, 4)
void gemm_bf16x3(const __nv_bfloat16* __restrict__ Ah, const __nv_bfloat16* __restrict__ Al,
                 const __nv_bfloat16* __restrict__ Bh, const __nv_bfloat16* __restrict__ Bl,
                 const float* __restrict__ bias, float* __restrict__ C,
                 __nv_bfloat16* __restrict__ Ch, __nv_bfloat16* __restrict__ Cl,
                 int M, int N, int K, int qcols)
{
    extern __shared__ __align__(16) char sm[];
    const uint32_t sb = smem_u32(sm);

    const int tid  = threadIdx.x;
    const int wid  = tid >> 5, lane = tid & 31;
    const int bm   = blockIdx.y * 64, bn = blockIdx.x * 64;
    const int wr   = wid * 16;
    const int g    = lane >> 2;
    const int cp2  = (lane & 3) * 2;
    const int m_   = lane >> 3, r_ = lane & 7;

    const __nv_bfloat16* aSrc[2] = { Ah + (size_t)bm * K, Al + (size_t)bm * K };
    const __nv_bfloat16* bSrc[2] = { Bh + (size_t)bn * K, Bl + (size_t)bn * K };

    const int lrow = tid >> 2, lcc = tid & 3;
    size_t  roff[2];
    uint32_t soff[2];
#pragma unroll
    for (int it = 0; it < 2; it++) {
        int row = lrow + it * 32;
        roff[it] = (size_t)row * K + lcc * 8;
        soff[it] = TADDR(row, lcc * 16);
    }

    const int cb0 = (m_ >> 1) * 16;
    uint32_t aoff[2], bhoff[4], bloff[4];
    {
        int row = wr + (m_ & 1) * 8 + r_;
        aoff[0] = (uint32_t)AH_O + TADDR(row, cb0);
        aoff[1] = (uint32_t)AL_O + TADDR(row, cb0);
    }
#pragma unroll
    for (int ntp = 0; ntp < 4; ntp++) {
        int row = ntp * 16 + (m_ & 1) * 8 + r_;
        bhoff[ntp] = (uint32_t)BH_O + TADDR(row, cb0);
        bloff[ntp] = (uint32_t)BL_O + TADDR(row, cb0);
    }

    float acc[8][4];
#pragma unroll
    for (int j = 0; j < 8; j++)
#pragma unroll
        for (int l = 0; l < 4; l++) acc[j][l] = 0.f;

    const int nch = K >> 5;     // 32

    auto stage_load = [&](int c, int slot) {
        const uint32_t stg = sb + (uint32_t)(slot * STG_B);
        const size_t koff = (size_t)c * 32;
#pragma unroll
        for (int it = 0; it < 2; it++) {
            cp16(stg + AH_O + soff[it], aSrc[0] + roff[it] + koff);
            cp16(stg + AL_O + soff[it], aSrc[1] + roff[it] + koff);
            cp16(stg + BH_O + soff[it], bSrc[0] + roff[it] + koff);
            cp16(stg + BL_O + soff[it], bSrc[1] + roff[it] + koff);
        }
        asm volatile("cp.async.commit_group;");
    };

    stage_load(0, 0);
    stage_load(1, 1);

    int slot_c  = 0;
    int slot_nx = 2;

    for (int c = 0; c < nch; c++) {
        if (c + 1 < nch) asm volatile("cp.async.wait_group 1;");
        else             asm volatile("cp.async.wait_group 0;");
        __syncthreads();

        if (c + 2 < nch) {
            stage_load(c + 2, slot_nx);
            if (++slot_nx == NSTG) slot_nx = 0;
        }

        const uint32_t stg = sb + (uint32_t)(slot_c * STG_B);
        if (++slot_c == NSTG) slot_c = 0;

#pragma unroll
        for (int kk = 0; kk < 2; kk++) {
            const uint32_t kx = kk ? 32u : 0u;
            uint32_t af[2][4];
            ldsm4(af[0], stg + (aoff[0] ^ kx));
            ldsm4(af[1], stg + (aoff[1] ^ kx));
#pragma unroll
            for (int ntp = 0; ntp < 4; ntp++) {
                uint32_t bh[4], bl[4];
                ldsm4(bh, stg + (bhoff[ntp] ^ kx));
                ldsm4(bl, stg + (bloff[ntp] ^ kx));
                mma2(acc[2 * ntp],     af[0], bh[0], bh[2]);
                mma2(acc[2 * ntp + 1], af[0], bh[1], bh[3]);
                mma2(acc[2 * ntp],     af[0], bl[0], bl[2]);
                mma2(acc[2 * ntp + 1], af[0], bl[1], bl[3]);
                mma2(acc[2 * ntp],     af[1], bh[0], bh[2]);
                mma2(acc[2 * ntp + 1], af[1], bh[1], bh[3]);
            }
        }
    }

#pragma unroll
    for (int nt = 0; nt < 8; nt++) {
        int col = bn + nt * 8 + cp2;
        int r0  = bm + wr + g;
        if (MODE == 0) {
            float b0 = bias ? bias[col] : 0.f;
            float b1 = bias ? bias[col + 1] : 0.f;
            float2 v0 = make_float2(acc[nt][0] + b0, acc[nt][1] + b1);
            float2 v1 = make_float2(acc[nt][2] + b0, acc[nt][3] + b1);
            *reinterpret_cast<float2*>(&C[(size_t)r0 * N + col])       = v0;
            *reinterpret_cast<float2*>(&C[(size_t)(r0 + 8) * N + col]) = v1;
        } else {
            float sc = (col < qcols) ? SC_Q : 1.0f;
            store_split(Ch, Cl, (size_t)r0 * N + col,       acc[nt][0] * sc, acc[nt][1] * sc);
            store_split(Ch, Cl, (size_t)(r0 + 8) * N + col, acc[nt][2] * sc, acc[nt][3] * sc);
        }
    }
}

// ---------------------------------------------------------------------------
// HMMA flash attention — full bf16x3 numerics, exp2 softmax.
// CTA = 64 queries / 4 warps / 128 threads.
// Smem-slim variant: Q is staged through the stage-1 buffer, fragments are
// extracted BEFORE the K/V pipeline starts, so no dedicated Q region.
// smem = 2 stages x 32KB = 64KB (+pad) -> 3 CTAs/SM (12 warps).
// ---------------------------------------------------------------------------
#define ASTG   32768
#define KH_B   0
#define KL_B   8192
#define VH_B   16384
#define VL_B   24576
#define ATTN_SMEM (2 * ASTG + 1024)   // 65.5 KB

__global__ __launch_bounds__(128, 3)
void attn_mma(const __nv_bfloat16* __restrict__ qvh, const __nv_bfloat16* __restrict__ qvl,
              __nv_bfloat16* __restrict__ oh, __nv_bfloat16* __restrict__ ol)
{
    extern __shared__ __align__(16) char asmem[];
    const uint32_t sb = (smem_u32(asmem) + 1023u) & ~1023u;

    const int tid  = threadIdx.x;
    const int wid  = tid >> 5, lane = tid & 31;
    const int b    = blockIdx.z, h = blockIdx.y;
    const int q0   = blockIdx.x * 64;
    const int g    = lane >> 2, t4 = lane & 3;
    const int wr   = wid * 16;
    const int m_   = lane >> 3, r_ = lane & 7;

    uint32_t qf[2][4][4];        // [hi/lo][ks][4] — register-resident Q

    // --- Q prologue: stage Q through the stage-1 buffer, extract fragments ---
    {
        const uint32_t qh_tmp = sb + ASTG;          // stage-1 KH region (8KB)
        const uint32_t ql_tmp = sb + ASTG + 8192;   // stage-1 KL region (8KB)
        const size_t qb = ((size_t)(b * SEQ + q0)) * QKVDIM + h * HDIM;
#pragma unroll
        for (int it = 0; it < 4; it++) {
            int idx = tid + it * 128;
            int row = idx >> 3, c = idx & 7;
            uint32_t off = SWZ128((uint32_t)(row * 128 + c * 16));
            cp16(qh_tmp + off, qvh + qb + (size_t)row * QKVDIM + c * 8);
            cp16(ql_tmp + off, qvl + qb + (size_t)row * QKVDIM + c * 8);
        }
        asm volatile("cp.async.commit_group;");
        asm volatile("cp.async.wait_group 0;");
        __syncthreads();
#pragma unroll
        for (int hl = 0; hl < 2; hl++)
#pragma unroll
            for (int ks = 0; ks < 4; ks++) {
                uint32_t off = SWZ128((uint32_t)(
                    (wr + (m_ & 1) * 8 + r_) * 128 + ks * 32 + (m_ >> 1) * 16));
                ldsm4(qf[hl][ks], (hl ? ql_tmp : qh_tmp) + off);
            }
        __syncthreads();   // all warps done reading Q before stage-1 overwrite
    }

    auto stage_load = [&](int kt, int s) {
        const size_t kb = ((size_t)(b * SEQ + kt * 64)) * QKVDIM + h * HDIM;
        const __nv_bfloat16* srcs[4] = {
            qvh + kb + EMBED,     qvl + kb + EMBED,
            qvh + kb + 2 * EMBED, qvl + kb + 2 * EMBED };
#pragma unroll
        for (int t = 0; t < 4; t++) {
#pragma unroll
            for (int it = 0; it < 4; it++) {
                int idx = tid + it * 128;
                int row = idx >> 3, c = idx & 7;
                uint32_t off = SWZ128((uint32_t)(row * 128 + c * 16));
                cp16(sb + s * ASTG + t * 8192 + off,
                     srcs[t] + (size_t)row * QKVDIM + c * 8);
            }
        }
        asm volatile("cp.async.commit_group;");
    };

    stage_load(0, 0);

    float oacc[8][4];
#pragma unroll
    for (int i = 0; i < 8; i++)
#pragma unroll
        for (int j = 0; j < 4; j++) oacc[i][j] = 0.f;
    float m0 = -INFINITY, m1 = -INFINITY, l0 = 0.f, l1 = 0.f;

    const int ntile = SEQ / 64;

    for (int c = 0; c < ntile; c++) {
        const int s = c & 1;
        if (c + 1 < ntile) {
            stage_load(c + 1, s ^ 1);
            asm volatile("cp.async.wait_group 1;");
        } else {
            asm volatile("cp.async.wait_group 0;");
        }
        __syncthreads();

        const uint32_t stgb = sb + s * ASTG;

        float sacc[8][4];
#pragma unroll
        for (int i = 0; i < 8; i++)
#pragma unroll
            for (int j = 0; j < 4; j++) sacc[i][j] = 0.f;

#pragma unroll
        for (int ks = 0; ks < 4; ks++) {
#pragma unroll
            for (int ntp = 0; ntp < 4; ntp++) {
                uint32_t off = SWZ128((uint32_t)(
                    (ntp * 16 + (m_ & 1) * 8 + r_) * 128 + ks * 32 + (m_ >> 1) * 16));
                uint32_t kh[4], kl[4];
                ldsm4(kh, stgb + KH_B + off);
                ldsm4(kl, stgb + KL_B + off);
                mma2(sacc[2 * ntp],     qf[0][ks], kh[0], kh[2]);
                mma2(sacc[2 * ntp + 1], qf[0][ks], kh[1], kh[3]);
                mma2(sacc[2 * ntp],     qf[0][ks], kl[0], kl[2]);
                mma2(sacc[2 * ntp + 1], qf[0][ks], kl[1], kl[3]);
                mma2(sacc[2 * ntp],     qf[1][ks], kh[0], kh[2]);
                mma2(sacc[2 * ntp + 1], qf[1][ks], kh[1], kh[3]);
            }
        }

        float tm0 = -INFINITY, tm1 = -INFINITY;
#pragma unroll
        for (int nt = 0; nt < 8; nt++) {
            tm0 = fmaxf(tm0, fmaxf(sacc[nt][0], sacc[nt][1]));
            tm1 = fmaxf(tm1, fmaxf(sacc[nt][2], sacc[nt][3]));
        }
        tm0 = fmaxf(tm0, __shfl_xor_sync(0xffffffffu, tm0, 1));
        tm0 = fmaxf(tm0, __shfl_xor_sync(0xffffffffu, tm0, 2));
        tm1 = fmaxf(tm1, __shfl_xor_sync(0xffffffffu, tm1, 1));
        tm1 = fmaxf(tm1, __shfl_xor_sync(0xffffffffu, tm1, 2));

        const float mn0 = fmaxf(m0, tm0), mn1 = fmaxf(m1, tm1);
        const float cr0 = exp2f(m0 - mn0), cr1 = exp2f(m1 - mn1);
        m0 = mn0; m1 = mn1;

        float rs0 = 0.f, rs1 = 0.f;
#pragma unroll
        for (int nt = 0; nt < 8; nt++) {
            sacc[nt][0] = exp2f(sacc[nt][0] - mn0); rs0 += sacc[nt][0];
            sacc[nt][1] = exp2f(sacc[nt][1] - mn0); rs0 += sacc[nt][1];
            sacc[nt][2] = exp2f(sacc[nt][2] - mn1); rs1 += sacc[nt][2];
            sacc[nt][3] = exp2f(sacc[nt][3] - mn1); rs1 += sacc[nt][3];
        }
        rs0 += __shfl_xor_sync(0xffffffffu, rs0, 1);
        rs0 += __shfl_xor_sync(0xffffffffu, rs0, 2);
        rs1 += __shfl_xor_sync(0xffffffffu, rs1, 1);
        rs1 += __shfl_xor_sync(0xffffffffu, rs1, 2);
        l0 = l0 * cr0 + rs0;
        l1 = l1 * cr1 + rs1;

#pragma unroll
        for (int nt = 0; nt < 8; nt++) {
            oacc[nt][0] *= cr0; oacc[nt][1] *= cr0;
            oacc[nt][2] *= cr1; oacc[nt][3] *= cr1;
        }

#pragma unroll
        for (int ks = 0; ks < 4; ks++) {
            const float* s0 = sacc[2 * ks];
            const float* s1 = sacc[2 * ks + 1];
            uint32_t pah[4], pal[4];
            {
                float v[8] = { s0[0], s0[1], s0[2], s0[3], s1[0], s1[1], s1[2], s1[3] };
#pragma unroll
                for (int i = 0; i < 4; i++) {
                    float x = v[2 * i], y = v[2 * i + 1];
                    float xh = __bfloat162float(__float2bfloat16(x));
                    float yh = __bfloat162float(__float2bfloat16(y));
                    pah[i] = packbf2(x, y);
                    pal[i] = packbf2(x - xh, y - yh);
                }
            }
#pragma unroll
            for (int ntp = 0; ntp < 4; ntp++) {
                uint32_t off = SWZ128((uint32_t)(
                    (ks * 16 + (m_ & 1) * 8 + r_) * 128 + ntp * 32 + (m_ >> 1) * 16));
                uint32_t vh[4], vl[4];
                ldsm4t(vh, stgb + VH_B + off);
                ldsm4t(vl, stgb + VL_B + off);
                mma2(oacc[2 * ntp],     pah, vh[0], vh[1]);
                mma2(oacc[2 * ntp + 1], pah, vh[2], vh[3]);
                mma2(oacc[2 * ntp],     pah, vl[0], vl[1]);
                mma2(oacc[2 * ntp + 1], pah, vl[2], vl[3]);
                mma2(oacc[2 * ntp],     pal, vh[0], vh[1]);
                mma2(oacc[2 * ntp + 1], pal, vh[2], vh[3]);
            }
        }
        __syncthreads();
    }

    const float il0 = 1.f / l0, il1 = 1.f / l1;
    const size_t ob0 = ((size_t)(b * SEQ + q0 + wr + g)) * EMBED + h * HDIM;
    const size_t ob1 = ob0 + (size_t)8 * EMBED;
#pragma unroll
    for (int nt = 0; nt < 8; nt++) {
        int d = nt * 8 + 2 * t4;
        store_split(oh, ol, ob0 + d, oacc[nt][0] * il0, oacc[nt][1] * il0);
        store_split(oh, ol, ob1 + d, oacc[nt][2] * il1, oacc[nt][3] * il1);
    }
}

// ---------------------------------------------------------------------------
extern "C" void kernel_launch(void* const* d_in, const int* in_sizes, int n_in,
                              void* d_out, int out_size)
{
    const float* x     = (const float*)d_in[0];
    const float* w_qkv = (const float*)d_in[1];
    const float* w_out = (const float*)d_in[2];
    const float* b_out = (const float*)d_in[3];
    float* out = (float*)d_out;

    __nv_bfloat16 *xh, *xl, *wqh, *wql, *woh, *wol, *qvh, *qvl, *ah, *al;
    cudaGetSymbolAddress((void**)&xh,  g_xh);  cudaGetSymbolAddress((void**)&xl,  g_xl);
    cudaGetSymbolAddress((void**)&wqh, g_wqh); cudaGetSymbolAddress((void**)&wql, g_wql);
    cudaGetSymbolAddress((void**)&woh, g_woh); cudaGetSymbolAddress((void**)&wol, g_wol);
    cudaGetSymbolAddress((void**)&qvh, g_qvh); cudaGetSymbolAddress((void**)&qvl, g_qvl);
    cudaGetSymbolAddress((void**)&ah,  g_ah);  cudaGetSymbolAddress((void**)&al,  g_al);

    cudaFuncSetAttribute(gemm_bf16x3<0>, cudaFuncAttributeMaxDynamicSharedMemorySize, GEMM_SMEM);
    cudaFuncSetAttribute(gemm_bf16x3<1>, cudaFuncAttributeMaxDynamicSharedMemorySize, GEMM_SMEM);
    cudaFuncSetAttribute(attn_mma, cudaFuncAttributeMaxDynamicSharedMemorySize, (int)ATTN_SMEM);

    // operand splits
    {
        int n4 = (MTOT * EMBED) / 4;
        cvt_split<<<(n4 + 255) / 256, 256>>>(x, xh, xl, n4);
    }
    {
        int n4 = (QKVDIM * EMBED) / 4;
        cvt_split<<<(n4 + 255) / 256, 256>>>(w_qkv, wqh, wql, n4);
    }
    {
        int n4 = (EMBED * EMBED) / 4;
        cvt_split<<<(n4 + 255) / 256, 256>>>(w_out, woh, wol, n4);
    }

    // 1) QKV projection -> split hi/lo, Q cols pre-scaled to log2 domain
    {
        dim3 grid(QKVDIM / 64, MTOT / 64);
        gemm_bf16x3<1><<<grid, 128, GEMM_SMEM>>>(xh, xl, wqh, wql, nullptr, nullptr,
                                                 qvh, qvl, MTOT, QKVDIM, GK, EMBED);
    }

    // 2) flash attention (HMMA, exp2 softmax, full bf16x3, 3 CTAs/SM)
    {
        dim3 grid(SEQ / 64, NHEADS, BATCH);
        attn_mma<<<grid, 128, ATTN_SMEM>>>(qvh, qvl, ah, al);
    }

    // 3) output projection + bias -> fp32 out
    {
        dim3 grid(EMBED / 64, MTOT / 64);
        gemm_bf16x3<0><<<grid, 128, GEMM_SMEM>>>(ah, al, woh, wol, b_out, out,
                                                 nullptr, nullptr, MTOT, EMBED, GK, 0);
    }
}

// round 16
// speedup vs baseline: 1.1001x; 1.0251x over previous
#include <cuda_runtime.h>
#include <cuda_bf16.h>
#include <math.h>
#include <stdint.h>

#define EMBED   1024
#define NHEADS  16
#define HDIM    64
#define SEQ     2048
#define BATCH   2
#define MTOT    (BATCH * SEQ)      // 4096
#define QKVDIM  (3 * EMBED)        // 3072
#define GK      1024
// 0.125 * log2(e): scores produced directly in log2 domain for exp2 softmax
#define SC_Q    0.18033688011112042f

typedef unsigned long long u64;

// ---------------------------------------------------------------------------
// Scratch (allocation-free __device__ globals)
// ---------------------------------------------------------------------------
__device__ __align__(16) __nv_bfloat16 g_xh [(size_t)MTOT  * EMBED];
__device__ __align__(16) __nv_bfloat16 g_xl [(size_t)MTOT  * EMBED];
__device__ __align__(16) __nv_bfloat16 g_wqh[(size_t)QKVDIM* EMBED];
__device__ __align__(16) __nv_bfloat16 g_wql[(size_t)QKVDIM* EMBED];
__device__ __align__(16) __nv_bfloat16 g_woh[(size_t)EMBED * EMBED];
__device__ __align__(16) __nv_bfloat16 g_wol[(size_t)EMBED * EMBED];
__device__ __align__(16) __nv_bfloat16 g_qvh[(size_t)MTOT  * QKVDIM];
__device__ __align__(16) __nv_bfloat16 g_qvl[(size_t)MTOT  * QKVDIM];
__device__ __align__(16) __nv_bfloat16 g_ah [(size_t)MTOT  * EMBED];
__device__ __align__(16) __nv_bfloat16 g_al [(size_t)MTOT  * EMBED];

// ---------------------------------------------------------------------------
// helpers
// ---------------------------------------------------------------------------
__device__ __forceinline__ uint32_t smem_u32(const void* p) {
    uint32_t a;
    asm("{ .reg .u64 t; cvta.to.shared.u64 t, %1; cvt.u32.u64 %0, t; }" : "=r"(a) : "l"(p));
    return a;
}
__device__ __forceinline__ void cp16(uint32_t s, const void* g) {
    asm volatile("cp.async.cg.shared.global [%0], [%1], 16;" :: "r"(s), "l"(g));
}
__device__ __forceinline__ void mma2(float* c, const uint32_t* a, uint32_t b0, uint32_t b1) {
    asm("mma.sync.aligned.m16n8k16.row.col.f32.bf16.bf16.f32 "
        "{%0,%1,%2,%3}, {%4,%5,%6,%7}, {%8,%9}, {%0,%1,%2,%3};"
        : "+f"(c[0]), "+f"(c[1]), "+f"(c[2]), "+f"(c[3])
        : "r"(a[0]), "r"(a[1]), "r"(a[2]), "r"(a[3]), "r"(b0), "r"(b1));
}
__device__ __forceinline__ void ldsm4(uint32_t* r, uint32_t addr) {
    asm volatile("ldmatrix.sync.aligned.m8n8.x4.shared.b16 {%0,%1,%2,%3}, [%4];"
        : "=r"(r[0]), "=r"(r[1]), "=r"(r[2]), "=r"(r[3]) : "r"(addr));
}
__device__ __forceinline__ void ldsm4t(uint32_t* r, uint32_t addr) {
    asm volatile("ldmatrix.sync.aligned.m8n8.x4.trans.shared.b16 {%0,%1,%2,%3}, [%4];"
        : "=r"(r[0]), "=r"(r[1]), "=r"(r[2]), "=r"(r[3]) : "r"(addr));
}
__device__ __forceinline__ uint32_t packbf2(float lo, float hi) {
    uint32_t d;
    asm("cvt.rn.bf16x2.f32 %0, %1, %2;" : "=r"(d) : "f"(hi), "f"(lo));
    return d;
}
// guaranteed single MUFU.EX2 (no libm slow path)
__device__ __forceinline__ float ex2f(float x) {
    float y;
    asm("ex2.approx.ftz.f32 %0, %1;" : "=f"(y) : "f"(x));
    return y;
}
#define SWZ128(x) ((x) ^ (((x) >> 3) & 0x70))
// 64B logical rows interleaved into 128B macro rows, then SW128
#define TADDR(row, cb) SWZ128((uint32_t)((((row) >> 1) * 128) + (((row) & 1) * 64) + (cb)))

// ---------------------------------------------------------------------------
// fp32 -> (bf16 hi, bf16 lo) split, 3 tensors in one launch
// ---------------------------------------------------------------------------
__global__ void cvt_split3(const float* __restrict__ in0, __nv_bfloat16* __restrict__ hi0,
                           __nv_bfloat16* __restrict__ lo0, int n0,
                           const float* __restrict__ in1, __nv_bfloat16* __restrict__ hi1,
                           __nv_bfloat16* __restrict__ lo1, int n1,
                           const float* __restrict__ in2, __nv_bfloat16* __restrict__ hi2,
                           __nv_bfloat16* __restrict__ lo2, int n2)
{
    int i = blockIdx.x * blockDim.x + threadIdx.x;
    const float* in;
    __nv_bfloat16 *hi, *lo;
    int idx;
    if (i < n0)            { in = in0; hi = hi0; lo = lo0; idx = i; }
    else if (i < n0 + n1)  { in = in1; hi = hi1; lo = lo1; idx = i - n0; }
    else if (i < n0 + n1 + n2) { in = in2; hi = hi2; lo = lo2; idx = i - n0 - n1; }
    else return;

    float4 v = reinterpret_cast<const float4*>(in)[idx];
    float h0 = __bfloat162float(__float2bfloat16(v.x));
    float h1 = __bfloat162float(__float2bfloat16(v.y));
    float h2 = __bfloat162float(__float2bfloat16(v.z));
    float h3 = __bfloat162float(__float2bfloat16(v.w));
    uint2 hv, lv;
    hv.x = packbf2(v.x, v.y);      hv.y = packbf2(v.z, v.w);
    lv.x = packbf2(v.x - h0, v.y - h1);
    lv.y = packbf2(v.z - h2, v.w - h3);
    reinterpret_cast<uint2*>(hi)[idx] = hv;
    reinterpret_cast<uint2*>(lo)[idx] = lv;
}

__device__ __forceinline__ void store_split(__nv_bfloat16* Ch, __nv_bfloat16* Cl,
                                            size_t off, float v0, float v1)
{
    float h0 = __bfloat162float(__float2bfloat16(v0));
    float h1 = __bfloat162float(__float2bfloat16(v1));
    *reinterpret_cast<uint32_t*>(&Ch[off]) = packbf2(v0, v1);
    *reinterpret_cast<uint32_t*>(&Cl[off]) = packbf2(v0 - h0, v1 - h1);
}

// ---------------------------------------------------------------------------
// HMMA bf16x3 GEMM (best measured config): CTA 64x64, 128 threads, BK=32,
// ldmatrix hoisted, 3-stage cp.async, 4 CTAs/SM.
// MODE 0: fp32 out + bias. MODE 1: split hi/lo out, cols<qcols scaled SC_Q.
// ---------------------------------------------------------------------------
#define AH_O   0
#define AL_O   4096
#define BH_O   8192
#define BL_O   12288
#define STG_B  16384                // bytes per stage
#define NSTG   3
#define GEMM_SMEM (NSTG * STG_B)    // 48 KB

template<int MODE>
__global__ __launch_bounds__(128, 4)
void gemm_bf16x3(const __nv_bfloat16* __restrict__ Ah, const __nv_bfloat16* __restrict__ Al,
                 const __nv_bfloat16* __restrict__ Bh, const __nv_bfloat16* __restrict__ Bl,
                 const float* __restrict__ bias, float* __restrict__ C,
                 __nv_bfloat16* __restrict__ Ch, __nv_bfloat16* __restrict__ Cl,
                 int M, int N, int K, int qcols)
{
    extern __shared__ __align__(16) char sm[];
    const uint32_t sb = smem_u32(sm);

    const int tid  = threadIdx.x;
    const int wid  = tid >> 5, lane = tid & 31;
    const int bm   = blockIdx.y * 64, bn = blockIdx.x * 64;
    const int wr   = wid * 16;
    const int g    = lane >> 2;
    const int cp2  = (lane & 3) * 2;
    const int m_   = lane >> 3, r_ = lane & 7;

    const __nv_bfloat16* aSrc[2] = { Ah + (size_t)bm * K, Al + (size_t)bm * K };
    const __nv_bfloat16* bSrc[2] = { Bh + (size_t)bn * K, Bl + (size_t)bn * K };

    const int lrow = tid >> 2, lcc = tid & 3;
    size_t  roff[2];
    uint32_t soff[2];
#pragma unroll
    for (int it = 0; it < 2; it++) {
        int row = lrow + it * 32;
        roff[it] = (size_t)row * K + lcc * 8;
        soff[it] = TADDR(row, lcc * 16);
    }

    const int cb0 = (m_ >> 1) * 16;
    uint32_t aoff[2], bhoff[4], bloff[4];
    {
        int row = wr + (m_ & 1) * 8 + r_;
        aoff[0] = (uint32_t)AH_O + TADDR(row, cb0);
        aoff[1] = (uint32_t)AL_O + TADDR(row, cb0);
    }
#pragma unroll
    for (int ntp = 0; ntp < 4; ntp++) {
        int row = ntp * 16 + (m_ & 1) * 8 + r_;
        bhoff[ntp] = (uint32_t)BH_O + TADDR(row, cb0);
        bloff[ntp] = (uint32_t)BL_O + TADDR(row, cb0);
    }

    float acc[8][4];
#pragma unroll
    for (int j = 0; j < 8; j++)
#pragma unroll
        for (int l = 0; l < 4; l++) acc[j][l] = 0.f;

    const int nch = K >> 5;     // 32

    auto stage_load = [&](int c, int slot) {
        const uint32_t stg = sb + (uint32_t)(slot * STG_B);
        const size_t koff = (size_t)c * 32;
#pragma unroll
        for (int it = 0; it < 2; it++) {
            cp16(stg + AH_O + soff[it], aSrc[0] + roff[it] + koff);
            cp16(stg + AL_O + soff[it], aSrc[1] + roff[it] + koff);
            cp16(stg + BH_O + soff[it], bSrc[0] + roff[it] + koff);
            cp16(stg + BL_O + soff[it], bSrc[1] + roff[it] + koff);
        }
        asm volatile("cp.async.commit_group;");
    };

    stage_load(0, 0);
    stage_load(1, 1);

    int slot_c  = 0;
    int slot_nx = 2;

    for (int c = 0; c < nch; c++) {
        if (c + 1 < nch) asm volatile("cp.async.wait_group 1;");
        else             asm volatile("cp.async.wait_group 0;");
        __syncthreads();

        if (c + 2 < nch) {
            stage_load(c + 2, slot_nx);
            if (++slot_nx == NSTG) slot_nx = 0;
        }

        const uint32_t stg = sb + (uint32_t)(slot_c * STG_B);
        if (++slot_c == NSTG) slot_c = 0;

#pragma unroll
        for (int kk = 0; kk < 2; kk++) {
            const uint32_t kx = kk ? 32u : 0u;
            uint32_t af[2][4];
            ldsm4(af[0], stg + (aoff[0] ^ kx));
            ldsm4(af[1], stg + (aoff[1] ^ kx));
#pragma unroll
            for (int ntp = 0; ntp < 4; ntp++) {
                uint32_t bh[4], bl[4];
                ldsm4(bh, stg + (bhoff[ntp] ^ kx));
                ldsm4(bl, stg + (bloff[ntp] ^ kx));
                mma2(acc[2 * ntp],     af[0], bh[0], bh[2]);
                mma2(acc[2 * ntp + 1], af[0], bh[1], bh[3]);
                mma2(acc[2 * ntp],     af[0], bl[0], bl[2]);
                mma2(acc[2 * ntp + 1], af[0], bl[1], bl[3]);
                mma2(acc[2 * ntp],     af[1], bh[0], bh[2]);
                mma2(acc[2 * ntp + 1], af[1], bh[1], bh[3]);
            }
        }
    }

#pragma unroll
    for (int nt = 0; nt < 8; nt++) {
        int col = bn + nt * 8 + cp2;
        int r0  = bm + wr + g;
        if (MODE == 0) {
            float b0 = bias ? bias[col] : 0.f;
            float b1 = bias ? bias[col + 1] : 0.f;
            float2 v0 = make_float2(acc[nt][0] + b0, acc[nt][1] + b1);
            float2 v1 = make_float2(acc[nt][2] + b0, acc[nt][3] + b1);
            *reinterpret_cast<float2*>(&C[(size_t)r0 * N + col])       = v0;
            *reinterpret_cast<float2*>(&C[(size_t)(r0 + 8) * N + col]) = v1;
        } else {
            float sc = (col < qcols) ? SC_Q : 1.0f;
            store_split(Ch, Cl, (size_t)r0 * N + col,       acc[nt][0] * sc, acc[nt][1] * sc);
            store_split(Ch, Cl, (size_t)(r0 + 8) * N + col, acc[nt][2] * sc, acc[nt][3] * sc);
        }
    }
}

// ---------------------------------------------------------------------------
// HMMA flash attention — full bf16x3 numerics, ex2.approx softmax.
// CTA = 64 queries / 4 warps / 128 threads, smem-slim (Q staged through
// stage-1 buffer), 3 CTAs/SM.
// ---------------------------------------------------------------------------
#define ASTG   32768
#define KH_B   0
#define KL_B   8192
#define VH_B   16384
#define VL_B   24576
#define ATTN_SMEM (2 * ASTG + 1024)   // 65.5 KB

__global__ __launch_bounds__(128, 3)
void attn_mma(const __nv_bfloat16* __restrict__ qvh, const __nv_bfloat16* __restrict__ qvl,
              __nv_bfloat16* __restrict__ oh, __nv_bfloat16* __restrict__ ol)
{
    extern __shared__ __align__(16) char asmem[];
    const uint32_t sb = (smem_u32(asmem) + 1023u) & ~1023u;

    const int tid  = threadIdx.x;
    const int wid  = tid >> 5, lane = tid & 31;
    const int b    = blockIdx.z, h = blockIdx.y;
    const int q0   = blockIdx.x * 64;
    const int g    = lane >> 2, t4 = lane & 3;
    const int wr   = wid * 16;
    const int m_   = lane >> 3, r_ = lane & 7;

    uint32_t qf[2][4][4];        // [hi/lo][ks][4] — register-resident Q

    // --- Q prologue: stage Q through the stage-1 buffer, extract fragments ---
    {
        const uint32_t qh_tmp = sb + ASTG;
        const uint32_t ql_tmp = sb + ASTG + 8192;
        const size_t qb = ((size_t)(b * SEQ + q0)) * QKVDIM + h * HDIM;
#pragma unroll
        for (int it = 0; it < 4; it++) {
            int idx = tid + it * 128;
            int row = idx >> 3, c = idx & 7;
            uint32_t off = SWZ128((uint32_t)(row * 128 + c * 16));
            cp16(qh_tmp + off, qvh + qb + (size_t)row * QKVDIM + c * 8);
            cp16(ql_tmp + off, qvl + qb + (size_t)row * QKVDIM + c * 8);
        }
        asm volatile("cp.async.commit_group;");
        asm volatile("cp.async.wait_group 0;");
        __syncthreads();
#pragma unroll
        for (int hl = 0; hl < 2; hl++)
#pragma unroll
            for (int ks = 0; ks < 4; ks++) {
                uint32_t off = SWZ128((uint32_t)(
                    (wr + (m_ & 1) * 8 + r_) * 128 + ks * 32 + (m_ >> 1) * 16));
                ldsm4(qf[hl][ks], (hl ? ql_tmp : qh_tmp) + off);
            }
        __syncthreads();
    }

    auto stage_load = [&](int kt, int s) {
        const size_t kb = ((size_t)(b * SEQ + kt * 64)) * QKVDIM + h * HDIM;
        const __nv_bfloat16* srcs[4] = {
            qvh + kb + EMBED,     qvl + kb + EMBED,
            qvh + kb + 2 * EMBED, qvl + kb + 2 * EMBED };
#pragma unroll
        for (int t = 0; t < 4; t++) {
#pragma unroll
            for (int it = 0; it < 4; it++) {
                int idx = tid + it * 128;
                int row = idx >> 3, c = idx & 7;
                uint32_t off = SWZ128((uint32_t)(row * 128 + c * 16));
                cp16(sb + s * ASTG + t * 8192 + off,
                     srcs[t] + (size_t)row * QKVDIM + c * 8);
            }
        }
        asm volatile("cp.async.commit_group;");
    };

    stage_load(0, 0);

    float oacc[8][4];
#pragma unroll
    for (int i = 0; i < 8; i++)
#pragma unroll
        for (int j = 0; j < 4; j++) oacc[i][j] = 0.f;
    float m0 = -INFINITY, m1 = -INFINITY, l0 = 0.f, l1 = 0.f;

    const int ntile = SEQ / 64;

    for (int c = 0; c < ntile; c++) {
        const int s = c & 1;
        if (c + 1 < ntile) {
            stage_load(c + 1, s ^ 1);
            asm volatile("cp.async.wait_group 1;");
        } else {
            asm volatile("cp.async.wait_group 0;");
        }
        __syncthreads();

        const uint32_t stgb = sb + s * ASTG;

        float sacc[8][4];
#pragma unroll
        for (int i = 0; i < 8; i++)
#pragma unroll
            for (int j = 0; j < 4; j++) sacc[i][j] = 0.f;

#pragma unroll
        for (int ks = 0; ks < 4; ks++) {
#pragma unroll
            for (int ntp = 0; ntp < 4; ntp++) {
                uint32_t off = SWZ128((uint32_t)(
                    (ntp * 16 + (m_ & 1) * 8 + r_) * 128 + ks * 32 + (m_ >> 1) * 16));
                uint32_t kh[4], kl[4];
                ldsm4(kh, stgb + KH_B + off);
                ldsm4(kl, stgb + KL_B + off);
                mma2(sacc[2 * ntp],     qf[0][ks], kh[0], kh[2]);
                mma2(sacc[2 * ntp + 1], qf[0][ks], kh[1], kh[3]);
                mma2(sacc[2 * ntp],     qf[0][ks], kl[0], kl[2]);
                mma2(sacc[2 * ntp + 1], qf[0][ks], kl[1], kl[3]);
                mma2(sacc[2 * ntp],     qf[1][ks], kh[0], kh[2]);
                mma2(sacc[2 * ntp + 1], qf[1][ks], kh[1], kh[3]);
            }
        }

        float tm0 = -INFINITY, tm1 = -INFINITY;
#pragma unroll
        for (int nt = 0; nt < 8; nt++) {
            tm0 = fmaxf(tm0, fmaxf(sacc[nt][0], sacc[nt][1]));
            tm1 = fmaxf(tm1, fmaxf(sacc[nt][2], sacc[nt][3]));
        }
        tm0 = fmaxf(tm0, __shfl_xor_sync(0xffffffffu, tm0, 1));
        tm0 = fmaxf(tm0, __shfl_xor_sync(0xffffffffu, tm0, 2));
        tm1 = fmaxf(tm1, __shfl_xor_sync(0xffffffffu, tm1, 1));
        tm1 = fmaxf(tm1, __shfl_xor_sync(0xffffffffu, tm1, 2));

        const float mn0 = fmaxf(m0, tm0), mn1 = fmaxf(m1, tm1);
        const float cr0 = ex2f(m0 - mn0), cr1 = ex2f(m1 - mn1);
        m0 = mn0; m1 = mn1;

        float rs0 = 0.f, rs1 = 0.f;
#pragma unroll
        for (int nt = 0; nt < 8; nt++) {
            sacc[nt][0] = ex2f(sacc[nt][0] - mn0); rs0 += sacc[nt][0];
            sacc[nt][1] = ex2f(sacc[nt][1] - mn0); rs0 += sacc[nt][1];
            sacc[nt][2] = ex2f(sacc[nt][2] - mn1); rs1 += sacc[nt][2];
            sacc[nt][3] = ex2f(sacc[nt][3] - mn1); rs1 += sacc[nt][3];
        }
        rs0 += __shfl_xor_sync(0xffffffffu, rs0, 1);
        rs0 += __shfl_xor_sync(0xffffffffu, rs0, 2);
        rs1 += __shfl_xor_sync(0xffffffffu, rs1, 1);
        rs1 += __shfl_xor_sync(0xffffffffu, rs1, 2);
        l0 = l0 * cr0 + rs0;
        l1 = l1 * cr1 + rs1;

#pragma unroll
        for (int nt = 0; nt < 8; nt++) {
            oacc[nt][0] *= cr0; oacc[nt][1] *= cr0;
            oacc[nt][2] *= cr1; oacc[nt][3] *= cr1;
        }

#pragma unroll
        for (int ks = 0; ks < 4; ks++) {
            const float* s0 = sacc[2 * ks];
            const float* s1 = sacc[2 * ks + 1];
            uint32_t pah[4], pal[4];
            {
                float v[8] = { s0[0], s0[1], s0[2], s0[3], s1[0], s1[1], s1[2], s1[3] };
#pragma unroll
                for (int i = 0; i < 4; i++) {
                    float x = v[2 * i], y = v[2 * i + 1];
                    float xh = __bfloat162float(__float2bfloat16(x));
                    float yh = __bfloat162float(__float2bfloat16(y));
                    pah[i] = packbf2(x, y);
                    pal[i] = packbf2(x - xh, y - yh);
                }
            }
#pragma unroll
            for (int ntp = 0; ntp < 4; ntp++) {
                uint32_t off = SWZ128((uint32_t)(
                    (ks * 16 + (m_ & 1) * 8 + r_) * 128 + ntp * 32 + (m_ >> 1) * 16));
                uint32_t vh[4], vl[4];
                ldsm4t(vh, stgb + VH_B + off);
                ldsm4t(vl, stgb + VL_B + off);
                mma2(oacc[2 * ntp],     pah, vh[0], vh[1]);
                mma2(oacc[2 * ntp + 1], pah, vh[2], vh[3]);
                mma2(oacc[2 * ntp],     pah, vl[0], vl[1]);
                mma2(oacc[2 * ntp + 1], pah, vl[2], vl[3]);
                mma2(oacc[2 * ntp],     pal, vh[0], vh[1]);
                mma2(oacc[2 * ntp + 1], pal, vh[2], vh[3]);
            }
        }
        __syncthreads();
    }

    const float il0 = 1.f / l0, il1 = 1.f / l1;
    const size_t ob0 = ((size_t)(b * SEQ + q0 + wr + g)) * EMBED + h * HDIM;
    const size_t ob1 = ob0 + (size_t)8 * EMBED;
#pragma unroll
    for (int nt = 0; nt < 8; nt++) {
        int d = nt * 8 + 2 * t4;
        store_split(oh, ol, ob0 + d, oacc[nt][0] * il0, oacc[nt][1] * il0);
        store_split(oh, ol, ob1 + d, oacc[nt][2] * il1, oacc[nt][3] * il1);
    }
}

// ---------------------------------------------------------------------------
extern "C" void kernel_launch(void* const* d_in, const int* in_sizes, int n_in,
                              void* d_out, int out_size)
{
    const float* x     = (const float*)d_in[0];
    const float* w_qkv = (const float*)d_in[1];
    const float* w_out = (const float*)d_in[2];
    const float* b_out = (const float*)d_in[3];
    float* out = (float*)d_out;

    __nv_bfloat16 *xh, *xl, *wqh, *wql, *woh, *wol, *qvh, *qvl, *ah, *al;
    cudaGetSymbolAddress((void**)&xh,  g_xh);  cudaGetSymbolAddress((void**)&xl,  g_xl);
    cudaGetSymbolAddress((void**)&wqh, g_wqh); cudaGetSymbolAddress((void**)&wql, g_wql);
    cudaGetSymbolAddress((void**)&woh, g_woh); cudaGetSymbolAddress((void**)&wol, g_wol);
    cudaGetSymbolAddress((void**)&qvh, g_qvh); cudaGetSymbolAddress((void**)&qvl, g_qvl);
    cudaGetSymbolAddress((void**)&ah,  g_ah);  cudaGetSymbolAddress((void**)&al,  g_al);

    cudaFuncSetAttribute(gemm_bf16x3<0>, cudaFuncAttributeMaxDynamicSharedMemorySize, GEMM_SMEM);
    cudaFuncSetAttribute(gemm_bf16x3<1>, cudaFuncAttributeMaxDynamicSharedMemorySize, GEMM_SMEM);
    cudaFuncSetAttribute(attn_mma, cudaFuncAttributeMaxDynamicSharedMemorySize, (int)ATTN_SMEM);

    // operand splits (single launch for all three tensors)
    {
        int n0 = (MTOT * EMBED) / 4;       // x
        int n1 = (QKVDIM * EMBED) / 4;     // w_qkv
        int n2 = (EMBED * EMBED) / 4;      // w_out
        int total = n0 + n1 + n2;
        cvt_split3<<<(total + 255) / 256, 256>>>(x, xh, xl, n0,
                                                 w_qkv, wqh, wql, n1,
                                                 w_out, woh, wol, n2);
    }

    // 1) QKV projection -> split hi/lo, Q cols pre-scaled to log2 domain
    {
        dim3 grid(QKVDIM / 64, MTOT / 64);
        gemm_bf16x3<1><<<grid, 128, GEMM_SMEM>>>(xh, xl, wqh, wql, nullptr, nullptr,
                                                 qvh, qvl, MTOT, QKVDIM, GK, EMBED);
    }

    // 2) flash attention (HMMA, ex2.approx softmax, full bf16x3)
    {
        dim3 grid(SEQ / 64, NHEADS, BATCH);
        attn_mma<<<grid, 128, ATTN_SMEM>>>(qvh, qvl, ah, al);
    }

    // 3) output projection + bias -> fp32 out
    {
        dim3 grid(EMBED / 64, MTOT / 64);
        gemm_bf16x3<0><<<grid, 128, GEMM_SMEM>>>(ah, al, woh, wol, b_out, out,
                                                 nullptr, nullptr, MTOT, EMBED, GK, 0);
    }
}